// round 11
// baseline (speedup 1.0000x reference)
#include <cuda_runtime.h>
#include <mma.h>
#include <math.h>
#include <stdint.h>

using namespace nvcuda;

#define N_NODES 10000
#define DIM     1024
#define NREL    8
#define NEDGE   80000
#define K1      9216
#define K2      2048

#define BM 128
#define BN 128
#define BK 32
#define NTHREADS 256
#define ALD 36                         /* A smem row stride (floats)  */
#define BLD 132                        /* B smem row stride (floats)  */
#define CLD 132                        /* epilogue staging stride     */
#define A_TILE_FLOATS (BM * ALD)       /* 4608 */
#define B_TILE_FLOATS (BK * BLD)       /* 4224 */
#define STAGE_FLOATS  (A_TILE_FLOATS + B_TILE_FLOATS)   /* 8832  */
#define SMEM_FLOATS   (2 * STAGE_FLOATS)                /* 17664 */
#define SMEM_BYTES    (SMEM_FLOATS * 4)                 /* 70656 */

/* Scratch device globals — PROVEN set only (R2/R7/R9). Adding more
   large statics correlates 3/3 with the 0.9113 failure signature.   */
__device__ float g_agg[(size_t)N_NODES * NREL * DIM];
__device__ float g_cnt[N_NODES * NREL];
__device__ float g_U[(size_t)N_NODES * DIM];
__device__ int   g_is64;

__device__ __forceinline__ float f2tf32(float f) {
    uint32_t r;
    asm("cvt.rna.tf32.f32 %0, %1;" : "=r"(r) : "f"(f));
    return __uint_as_float(r);
}

/* ================= prep kernels (verbatim from passing rounds) ===== */
__global__ void detect_kernel(const int* __restrict__ ei) {
    if (threadIdx.x == 0 && blockIdx.x == 0) {
        int allzero = 1;
        for (int i = 1; i < 4096; i += 2)
            if (ei[i] != 0) { allzero = 0; break; }
        g_is64 = allzero;
    }
}

__global__ void zero_scratch_kernel() {
    size_t idx    = (size_t)blockIdx.x * blockDim.x + threadIdx.x;
    size_t stride = (size_t)gridDim.x * blockDim.x;
    float4* agg4 = reinterpret_cast<float4*>(g_agg);
    const size_t nagg4 = (size_t)N_NODES * NREL * DIM / 4;
    for (size_t i = idx; i < nagg4; i += stride)
        agg4[i] = make_float4(0.f, 0.f, 0.f, 0.f);
    float4* cnt4 = reinterpret_cast<float4*>(g_cnt);
    const size_t ncnt4 = (size_t)N_NODES * NREL / 4;
    for (size_t i = idx; i < ncnt4; i += stride)
        cnt4[i] = make_float4(0.f, 0.f, 0.f, 0.f);
}

__global__ __launch_bounds__(256)
void scatter_kernel(const float* __restrict__ x,
                    const void* __restrict__ edge_index,
                    const void* __restrict__ edge_type) {
    int e = blockIdx.x;
    int src, dst, r;
    if (g_is64) {
        const long long* ei = (const long long*)edge_index;
        const long long* et = (const long long*)edge_type;
        src = (int)ei[e]; dst = (int)ei[NEDGE + e]; r = (int)et[e];
    } else {
        const int* ei = (const int*)edge_index;
        const int* et = (const int*)edge_type;
        src = ei[e]; dst = ei[NEDGE + e]; r = et[e];
    }
    const float4* xs = reinterpret_cast<const float4*>(x + (size_t)src * DIM);
    float* out = g_agg + ((size_t)dst * NREL + r) * DIM;
    int t = threadIdx.x;
    float4 v = xs[t];
    atomicAdd(out + t * 4 + 0, v.x);
    atomicAdd(out + t * 4 + 1, v.y);
    atomicAdd(out + t * 4 + 2, v.z);
    atomicAdd(out + t * 4 + 3, v.w);
    if (t == 0)
        atomicAdd(&g_cnt[dst * NREL + r], 1.0f);
}

/* ================= WMMA tf32 GEMM ==================================
   R7's proven pipeline (register prefetch, double-buffered smem,
   rounding + mean-normalization fused at the STS step, B in native
   row-major layout) with occupancy forced to 2 CTAs/SM.
   MODE 0: U = [x | mean] @ [root ; weight] + bias     (K = 9216)
   MODE 1: z = [u | x] @ w_gate + b_gate; fused gate   (K = 2048)      */
template <int MODE>
__global__ __launch_bounds__(NTHREADS, 2)
void gemm_wmma(const float* __restrict__ x,
               const float* __restrict__ B0,      /* root   | w_gate  */
               const float* __restrict__ B1,      /* weight | unused  */
               const float* __restrict__ bvec,
               float* __restrict__ out) {
    extern __shared__ float smem[];
    const int tid = threadIdx.x;
    const int wid = tid >> 5;
    const int m0  = blockIdx.y * BM;
    const int n0  = blockIdx.x * BN;
    const int KDIM = MODE ? K2 : K1;
    const int NC   = KDIM / BK;

    float* Abuf[2] = { smem,                 smem + STAGE_FLOATS };
    float* Bbuf[2] = { smem + A_TILE_FLOATS, smem + STAGE_FLOATS + A_TILE_FLOATS };

    const int wm = (wid & 3) * 32;     /* warp rows: 2 x 16 */
    const int wn = (wid >> 2) * 64;    /* warp cols: 4 x 16 */

    wmma::fragment<wmma::accumulator, 16, 16, 8, float> acc[2][4];
#pragma unroll
    for (int mt = 0; mt < 2; mt++)
#pragma unroll
        for (int nt = 0; nt < 4; nt++)
            wmma::fill_fragment(acc[mt][nt], 0.0f);

    float4 ra[4], rb[4];

    /* global -> registers (prefetch) */
    auto ldg_tile = [&](int ci) {
        const int k0 = ci * BK;
#pragma unroll
        for (int t = 0; t < 4; t++) {
            int idx = tid + t * NTHREADS;
            int row = idx >> 3;
            int c4  = (idx & 7) << 2;
            int grow = m0 + row;
            float4 v = make_float4(0.f, 0.f, 0.f, 0.f);
            if (grow < N_NODES) {
                int k = k0 + c4;
                if (MODE == 0) {
                    if (k < DIM) {
                        v = *reinterpret_cast<const float4*>(x + (size_t)grow * DIM + k);
                    } else {
                        int kk = k - DIM;
                        int r  = kk >> 10;
                        float s = 1.0f / fmaxf(g_cnt[grow * NREL + r], 1.0f);
                        float4 a = *reinterpret_cast<const float4*>(
                            g_agg + (size_t)grow * (NREL * DIM) + kk);
                        v.x = a.x * s; v.y = a.y * s; v.z = a.z * s; v.w = a.w * s;
                    }
                } else {
                    const float* Ap = (k < DIM)
                        ? (g_U + (size_t)grow * DIM + k)
                        : (x + (size_t)grow * DIM + (k - DIM));
                    v = *reinterpret_cast<const float4*>(Ap);
                }
            }
            ra[t] = v;
        }
#pragma unroll
        for (int t = 0; t < 4; t++) {
            int idx = tid + t * NTHREADS;
            int kr  = idx >> 5;
            int c4  = (idx & 31) << 2;
            int k   = k0 + kr;
            const float* src;
            if (MODE == 0)
                src = (k < DIM) ? (B0 + (size_t)k * DIM + n0 + c4)
                                : (B1 + (size_t)(k - DIM) * DIM + n0 + c4);
            else
                src = B0 + (size_t)k * DIM + n0 + c4;
            rb[t] = *reinterpret_cast<const float4*>(src);
        }
    };

    /* registers -> smem with tf32 rounding */
    auto st_tile = [&](int s) {
#pragma unroll
        for (int t = 0; t < 4; t++) {
            int idx = tid + t * NTHREADS;
            int row = idx >> 3;
            int c4  = (idx & 7) << 2;
            float* p = Abuf[s] + row * ALD + c4;
            p[0] = f2tf32(ra[t].x); p[1] = f2tf32(ra[t].y);
            p[2] = f2tf32(ra[t].z); p[3] = f2tf32(ra[t].w);
        }
#pragma unroll
        for (int t = 0; t < 4; t++) {
            int idx = tid + t * NTHREADS;
            int kr  = idx >> 5;
            int c4  = (idx & 31) << 2;
            float* p = Bbuf[s] + kr * BLD + c4;
            p[0] = f2tf32(rb[t].x); p[1] = f2tf32(rb[t].y);
            p[2] = f2tf32(rb[t].z); p[3] = f2tf32(rb[t].w);
        }
    };

    ldg_tile(0);

    for (int ci = 0; ci < NC; ci++) {
        const int s = ci & 1;
        st_tile(s);
        __syncthreads();
        if (ci + 1 < NC) ldg_tile(ci + 1);   /* LDGs retire under compute */

#pragma unroll
        for (int kk = 0; kk < 4; kk++) {
            wmma::fragment<wmma::matrix_b, 16, 16, 8,
                           wmma::precision::tf32, wmma::row_major> fb[4];
#pragma unroll
            for (int nt = 0; nt < 4; nt++)
                wmma::load_matrix_sync(fb[nt], Bbuf[s] + (kk * 8) * BLD + wn + nt * 16, BLD);
#pragma unroll
            for (int mt = 0; mt < 2; mt++) {
                wmma::fragment<wmma::matrix_a, 16, 16, 8,
                               wmma::precision::tf32, wmma::row_major> fa;
                wmma::load_matrix_sync(fa, Abuf[s] + (wm + mt * 16) * ALD + kk * 8, ALD);
#pragma unroll
                for (int nt = 0; nt < 4; nt++)
                    wmma::mma_sync(acc[mt][nt], fa, fb[nt], acc[mt][nt]);
            }
        }
        /* one sync per iteration: the collective sync at iter ci+1 fences
           iter ci's readers of buffer s from iter ci+2's writers of s.   */
    }

    /* ---- epilogue: stage accumulators in smem, then elementwise ---- */
    __syncthreads();
    float* stg = smem;                       /* 128 x CLD, reuses tiles */
#pragma unroll
    for (int mt = 0; mt < 2; mt++)
#pragma unroll
        for (int nt = 0; nt < 4; nt++)
            wmma::store_matrix_sync(stg + (wm + mt * 16) * CLD + wn + nt * 16,
                                    acc[mt][nt], CLD, wmma::mem_row_major);
    __syncthreads();

#pragma unroll
    for (int t = 0; t < 16; t++) {
        int idx = tid + t * NTHREADS;        /* 4096 float4 = 128x128 */
        int row = idx >> 5;
        int c4  = (idx & 31) << 2;
        int grow = m0 + row;
        if (grow >= N_NODES) continue;
        int gc = n0 + c4;
        const float* sp = stg + row * CLD + c4;
        float4 bv = *reinterpret_cast<const float4*>(bvec + gc);
        float z0 = sp[0] + bv.x, z1 = sp[1] + bv.y;
        float z2 = sp[2] + bv.z, z3 = sp[3] + bv.w;
        size_t o = (size_t)grow * DIM + gc;
        if (MODE == 0) {
            *reinterpret_cast<float4*>(g_U + o) = make_float4(z0, z1, z2, z3);
        } else {
            float4 u4 = *reinterpret_cast<const float4*>(g_U + o);
            float4 x4 = *reinterpret_cast<const float4*>(x + o);
            float h0 = tanhf(u4.x) * z0 + x4.x * (1.0f - z0);
            float h1 = tanhf(u4.y) * z1 + x4.y * (1.0f - z1);
            float h2 = tanhf(u4.z) * z2 + x4.z * (1.0f - z2);
            float h3 = tanhf(u4.w) * z3 + x4.w * (1.0f - z3);
            *reinterpret_cast<float4*>(out + o) = make_float4(h0, h1, h2, h3);
        }
    }
}

/* ================= launch ================= */
extern "C" void kernel_launch(void* const* d_in, const int* in_sizes, int n_in,
                              void* d_out, int out_size) {
    const float* x      = (const float*)d_in[0];
    const void*  ei     = d_in[1];
    const void*  et     = d_in[2];
    const float* weight = (const float*)d_in[3];
    const float* root   = (const float*)d_in[4];
    const float* bias   = (const float*)d_in[5];
    const float* w_gate = (const float*)d_in[6];
    const float* b_gate = (const float*)d_in[7];
    float*       out    = (float*)d_out;

    cudaFuncSetAttribute(gemm_wmma<0>, cudaFuncAttributeMaxDynamicSharedMemorySize, SMEM_BYTES);
    cudaFuncSetAttribute(gemm_wmma<1>, cudaFuncAttributeMaxDynamicSharedMemorySize, SMEM_BYTES);

    detect_kernel<<<1, 32>>>((const int*)ei);
    zero_scratch_kernel<<<1024, 256>>>();
    scatter_kernel<<<NEDGE, 256>>>(x, ei, et);

    dim3 grid(DIM / BN, (N_NODES + BM - 1) / BM);   /* 8 x 79 */
    gemm_wmma<0><<<grid, NTHREADS, SMEM_BYTES>>>(x, root, weight, bias, nullptr);
    gemm_wmma<1><<<grid, NTHREADS, SMEM_BYTES>>>(x, w_gate, nullptr, b_gate, out);
}

// round 12
// speedup vs baseline: 1.0682x; 1.0682x over previous
#include <cuda_runtime.h>
#include <mma.h>
#include <math.h>
#include <stdint.h>

using namespace nvcuda;

#define N_NODES 10000
#define DIM     1024
#define NREL    8
#define NEDGE   80000
#define K1      9216
#define K2      2048

#define BM 128
#define BN 128
#define BK 16
#define NTHREADS 256
#define ALD 20                         /* A smem row stride (floats)  */
#define BLD 132                        /* B smem row stride (floats)  */
#define CLD 132                        /* epilogue staging stride     */
#define A_TILE_FLOATS (BM * ALD)       /* 2560 */
#define B_TILE_FLOATS (BK * BLD)       /* 2112 */
#define STAGE_FLOATS  (A_TILE_FLOATS + B_TILE_FLOATS)   /* 4672 */
#define SMEM_BYTES    70656            /* >= 2*stages (37376) and 128*CLD*4 (67584) */

/* Scratch device globals — PROVEN set only. Staging inputs (esp. w_gate)
   through extra globals correlates 3/3 with the 0.9113 failure.        */
__device__ float g_agg[(size_t)N_NODES * NREL * DIM];
__device__ float g_cnt[N_NODES * NREL];
__device__ float g_U[(size_t)N_NODES * DIM];
__device__ int   g_is64;

__device__ __forceinline__ float f2tf32(float f) {
    uint32_t r;
    asm("cvt.rna.tf32.f32 %0, %1;" : "=r"(r) : "f"(f));
    return __uint_as_float(r);
}

/* ================= prep kernels (verbatim, proven) ================= */
__global__ void detect_kernel(const int* __restrict__ ei) {
    if (threadIdx.x == 0 && blockIdx.x == 0) {
        int allzero = 1;
        for (int i = 1; i < 4096; i += 2)
            if (ei[i] != 0) { allzero = 0; break; }
        g_is64 = allzero;
    }
}

__global__ void zero_scratch_kernel() {
    size_t idx    = (size_t)blockIdx.x * blockDim.x + threadIdx.x;
    size_t stride = (size_t)gridDim.x * blockDim.x;
    float4* agg4 = reinterpret_cast<float4*>(g_agg);
    const size_t nagg4 = (size_t)N_NODES * NREL * DIM / 4;
    for (size_t i = idx; i < nagg4; i += stride)
        agg4[i] = make_float4(0.f, 0.f, 0.f, 0.f);
    float4* cnt4 = reinterpret_cast<float4*>(g_cnt);
    const size_t ncnt4 = (size_t)N_NODES * NREL / 4;
    for (size_t i = idx; i < ncnt4; i += stride)
        cnt4[i] = make_float4(0.f, 0.f, 0.f, 0.f);
}

__global__ __launch_bounds__(256)
void scatter_kernel(const float* __restrict__ x,
                    const void* __restrict__ edge_index,
                    const void* __restrict__ edge_type) {
    int e = blockIdx.x;
    int src, dst, r;
    if (g_is64) {
        const long long* ei = (const long long*)edge_index;
        const long long* et = (const long long*)edge_type;
        src = (int)ei[e]; dst = (int)ei[NEDGE + e]; r = (int)et[e];
    } else {
        const int* ei = (const int*)edge_index;
        const int* et = (const int*)edge_type;
        src = ei[e]; dst = ei[NEDGE + e]; r = et[e];
    }
    const float4* xs = reinterpret_cast<const float4*>(x + (size_t)src * DIM);
    float* out = g_agg + ((size_t)dst * NREL + r) * DIM;
    int t = threadIdx.x;
    float4 v = xs[t];
    atomicAdd(out + t * 4 + 0, v.x);
    atomicAdd(out + t * 4 + 1, v.y);
    atomicAdd(out + t * 4 + 2, v.z);
    atomicAdd(out + t * 4 + 3, v.w);
    if (t == 0)
        atomicAdd(&g_cnt[dst * NREL + r], 1.0f);
}

/* ================= WMMA tf32 GEMM ==================================
   Register-prefetch double-buffer pipeline (R7-proven), BK=16 so the
   prefetch fits the 128-reg budget at occupancy 2 — no spills.
   MODE 0: U = [x | mean] @ [root ; weight] + bias     (K = 9216)
   MODE 1: z = [u | x] @ w_gate + b_gate; fused gate   (K = 2048)      */
template <int MODE>
__global__ __launch_bounds__(NTHREADS, 2)
void gemm_wmma(const float* __restrict__ x,
               const float* __restrict__ B0,      /* root   | w_gate  */
               const float* __restrict__ B1,      /* weight | unused  */
               const float* __restrict__ bvec,
               float* __restrict__ out) {
    extern __shared__ float smem[];
    const int tid = threadIdx.x;
    const int wid = tid >> 5;
    const int m0  = blockIdx.y * BM;
    const int n0  = blockIdx.x * BN;
    const int KDIM = MODE ? K2 : K1;
    const int NC   = KDIM / BK;

    float* Abuf[2] = { smem,                 smem + STAGE_FLOATS };
    float* Bbuf[2] = { smem + A_TILE_FLOATS, smem + STAGE_FLOATS + A_TILE_FLOATS };

    const int wm = (wid & 3) * 32;     /* warp rows: 2 x 16 */
    const int wn = (wid >> 2) * 64;    /* warp cols: 4 x 16 */

    wmma::fragment<wmma::accumulator, 16, 16, 8, float> acc[2][4];
#pragma unroll
    for (int mt = 0; mt < 2; mt++)
#pragma unroll
        for (int nt = 0; nt < 4; nt++)
            wmma::fill_fragment(acc[mt][nt], 0.0f);

    float4 ra[2], rb[2];

    /* global -> registers (prefetch): A 128x16, B 16x128 */
    auto ldg_tile = [&](int ci) {
        const int k0 = ci * BK;
#pragma unroll
        for (int t = 0; t < 2; t++) {
            int idx = tid + t * NTHREADS;
            int row = idx >> 2;                  /* 4 float4 per A row */
            int c4  = (idx & 3) << 2;
            int grow = m0 + row;
            float4 v = make_float4(0.f, 0.f, 0.f, 0.f);
            if (grow < N_NODES) {
                int k = k0 + c4;
                if (MODE == 0) {
                    if (k < DIM) {
                        v = *reinterpret_cast<const float4*>(x + (size_t)grow * DIM + k);
                    } else {
                        int kk = k - DIM;
                        int r  = kk >> 10;
                        float s = 1.0f / fmaxf(g_cnt[grow * NREL + r], 1.0f);
                        float4 a = *reinterpret_cast<const float4*>(
                            g_agg + (size_t)grow * (NREL * DIM) + kk);
                        v.x = a.x * s; v.y = a.y * s; v.z = a.z * s; v.w = a.w * s;
                    }
                } else {
                    const float* Ap = (k < DIM)
                        ? (g_U + (size_t)grow * DIM + k)
                        : (x + (size_t)grow * DIM + (k - DIM));
                    v = *reinterpret_cast<const float4*>(Ap);
                }
            }
            ra[t] = v;
        }
#pragma unroll
        for (int t = 0; t < 2; t++) {
            int idx = tid + t * NTHREADS;
            int kr  = idx >> 5;                  /* 0..15 */
            int c4  = (idx & 31) << 2;
            int k   = k0 + kr;
            const float* src;
            if (MODE == 0)
                src = (k < DIM) ? (B0 + (size_t)k * DIM + n0 + c4)
                                : (B1 + (size_t)(k - DIM) * DIM + n0 + c4);
            else
                src = B0 + (size_t)k * DIM + n0 + c4;
            rb[t] = *reinterpret_cast<const float4*>(src);
        }
    };

    /* registers -> smem with tf32 rounding */
    auto st_tile = [&](int s) {
#pragma unroll
        for (int t = 0; t < 2; t++) {
            int idx = tid + t * NTHREADS;
            int row = idx >> 2;
            int c4  = (idx & 3) << 2;
            float* p = Abuf[s] + row * ALD + c4;
            p[0] = f2tf32(ra[t].x); p[1] = f2tf32(ra[t].y);
            p[2] = f2tf32(ra[t].z); p[3] = f2tf32(ra[t].w);
        }
#pragma unroll
        for (int t = 0; t < 2; t++) {
            int idx = tid + t * NTHREADS;
            int kr  = idx >> 5;
            int c4  = (idx & 31) << 2;
            float* p = Bbuf[s] + kr * BLD + c4;
            p[0] = f2tf32(rb[t].x); p[1] = f2tf32(rb[t].y);
            p[2] = f2tf32(rb[t].z); p[3] = f2tf32(rb[t].w);
        }
    };

    ldg_tile(0);

    for (int ci = 0; ci < NC; ci++) {
        const int s = ci & 1;
        st_tile(s);
        __syncthreads();
        if (ci + 1 < NC) ldg_tile(ci + 1);   /* LDGs retire under MMA */

#pragma unroll
        for (int kk = 0; kk < 2; kk++) {
            wmma::fragment<wmma::matrix_b, 16, 16, 8,
                           wmma::precision::tf32, wmma::row_major> fb[4];
#pragma unroll
            for (int nt = 0; nt < 4; nt++)
                wmma::load_matrix_sync(fb[nt], Bbuf[s] + (kk * 8) * BLD + wn + nt * 16, BLD);
#pragma unroll
            for (int mt = 0; mt < 2; mt++) {
                wmma::fragment<wmma::matrix_a, 16, 16, 8,
                               wmma::precision::tf32, wmma::row_major> fa;
                wmma::load_matrix_sync(fa, Abuf[s] + (wm + mt * 16) * ALD + kk * 8, ALD);
#pragma unroll
                for (int nt = 0; nt < 4; nt++)
                    wmma::mma_sync(acc[mt][nt], fa, fb[nt], acc[mt][nt]);
            }
        }
        /* single sync/iter: sync at iter ci+1 fences ci's readers of
           buffer s from ci+2's writers of s (proven R7/R11). */
    }

    /* ---- epilogue: stage accumulators in smem, then elementwise ---- */
    __syncthreads();
    float* stg = smem;
#pragma unroll
    for (int mt = 0; mt < 2; mt++)
#pragma unroll
        for (int nt = 0; nt < 4; nt++)
            wmma::store_matrix_sync(stg + (wm + mt * 16) * CLD + wn + nt * 16,
                                    acc[mt][nt], CLD, wmma::mem_row_major);
    __syncthreads();

#pragma unroll
    for (int t = 0; t < 16; t++) {
        int idx = tid + t * NTHREADS;
        int row = idx >> 5;
        int c4  = (idx & 31) << 2;
        int grow = m0 + row;
        if (grow >= N_NODES) continue;
        int gc = n0 + c4;
        const float* sp = stg + row * CLD + c4;
        float4 bv = *reinterpret_cast<const float4*>(bvec + gc);
        float z0 = sp[0] + bv.x, z1 = sp[1] + bv.y;
        float z2 = sp[2] + bv.z, z3 = sp[3] + bv.w;
        size_t o = (size_t)grow * DIM + gc;
        if (MODE == 0) {
            *reinterpret_cast<float4*>(g_U + o) = make_float4(z0, z1, z2, z3);
        } else {
            float4 u4 = *reinterpret_cast<const float4*>(g_U + o);
            float4 x4 = *reinterpret_cast<const float4*>(x + o);
            float h0 = tanhf(u4.x) * z0 + x4.x * (1.0f - z0);
            float h1 = tanhf(u4.y) * z1 + x4.y * (1.0f - z1);
            float h2 = tanhf(u4.z) * z2 + x4.z * (1.0f - z2);
            float h3 = tanhf(u4.w) * z3 + x4.w * (1.0f - z3);
            *reinterpret_cast<float4*>(out + o) = make_float4(h0, h1, h2, h3);
        }
    }
}

/* ================= launch ================= */
extern "C" void kernel_launch(void* const* d_in, const int* in_sizes, int n_in,
                              void* d_out, int out_size) {
    const float* x      = (const float*)d_in[0];
    const void*  ei     = d_in[1];
    const void*  et     = d_in[2];
    const float* weight = (const float*)d_in[3];
    const float* root   = (const float*)d_in[4];
    const float* bias   = (const float*)d_in[5];
    const float* w_gate = (const float*)d_in[6];
    const float* b_gate = (const float*)d_in[7];
    float*       out    = (float*)d_out;

    cudaFuncSetAttribute(gemm_wmma<0>, cudaFuncAttributeMaxDynamicSharedMemorySize, SMEM_BYTES);
    cudaFuncSetAttribute(gemm_wmma<1>, cudaFuncAttributeMaxDynamicSharedMemorySize, SMEM_BYTES);

    detect_kernel<<<1, 32>>>((const int*)ei);
    zero_scratch_kernel<<<1024, 256>>>();
    scatter_kernel<<<NEDGE, 256>>>(x, ei, et);

    dim3 grid(DIM / BN, (N_NODES + BM - 1) / BM);   /* 8 x 79 */
    gemm_wmma<0><<<grid, NTHREADS, SMEM_BYTES>>>(x, root, weight, bias, nullptr);
    gemm_wmma<1><<<grid, NTHREADS, SMEM_BYTES>>>(x, w_gate, nullptr, b_gate, out);
}